// round 9
// baseline (speedup 1.0000x reference)
#include <cuda_runtime.h>

#define SEQ   1024
#define BATCH 512
#define INF   128
#define HID   256

typedef unsigned long long u64;

__device__ __forceinline__ u64 pack2(float lo, float hi) {
    u64 r; asm("mov.b64 %0, {%1, %2};" : "=l"(r) : "f"(lo), "f"(hi)); return r;
}
__device__ __forceinline__ void unpack2(u64 v, float& lo, float& hi) {
    asm("mov.b64 {%0, %1}, %2;" : "=f"(lo), "=f"(hi) : "l"(v));
}
__device__ __forceinline__ u64 ffma2(u64 a, u64 b, u64 c) {
    u64 d; asm("fma.rn.f32x2 %0, %1, %2, %3;" : "=l"(d) : "l"(a), "l"(b), "l"(c));
    return d;
}
__device__ __forceinline__ float sum2(u64 v) {
    float lo, hi; unpack2(v, lo, hi); return lo + hi;
}

// ---------------------------------------------------------------------------
// Kernel 1 (unchanged from R8 — measured at the plain-FFMA floor):
// x_proj = input @ W_in + (b_in + b_hh) -> d_out.
// ---------------------------------------------------------------------------
#define XROW 136

__global__ void __launch_bounds__(512, 1) xproj_kernel(
    const float* __restrict__ input, const float* __restrict__ Win,
    const float* __restrict__ b_in,  const float* __restrict__ b_hh,
    float* __restrict__ out)
{
    __shared__ float xs[2][8 * XROW];
    const int t     = threadIdx.x;
    const int j     = t >> 1;
    const int khalf = t & 1;
    const int koff  = khalf * 64;

    u64 W2[32];
#pragma unroll
    for (int k2 = 0; k2 < 32; ++k2)
        W2[k2] = pack2(Win[(koff + 2 * k2) * HID + j],
                       Win[(koff + 2 * k2 + 1) * HID + j]);
    const float bias = b_in[j] + b_hh[j];

    const int srow = t >> 6;
    const int sk   = (t & 63) * 2;
    const int sdst = srow * XROW + (sk >> 6) * 68 + (sk & 63);

    const int nchunks = (SEQ * BATCH) / 8;
    int c = blockIdx.x;
    if (c >= nchunks) return;

    *(float2*)&xs[0][sdst] = *(const float2*)(input + (long)c * 1024 + srow * 128 + sk);
    __syncthreads();

    int p = 0;
    while (c < nchunks) {
        const int  cn  = c + gridDim.x;
        const bool has = (cn < nchunks);
        float2 nxt;
        if (has) nxt = *(const float2*)(input + (long)cn * 1024 + srow * 128 + sk);

        u64 acc[8];
#pragma unroll
        for (int r = 0; r < 8; ++r) acc[r] = 0ull;

        const float* xb = xs[p];
#pragma unroll
        for (int k4 = 0; k4 < 16; ++k4) {
#pragma unroll
            for (int r = 0; r < 8; ++r) {
                ulonglong2 h2 = *(const ulonglong2*)(xb + r * XROW + khalf * 68 + 4 * k4);
                acc[r] = ffma2(W2[2 * k4 + 0], h2.x, acc[r]);
                acc[r] = ffma2(W2[2 * k4 + 1], h2.y, acc[r]);
            }
        }

        float s[8];
#pragma unroll
        for (int r = 0; r < 8; ++r) {
            s[r] = sum2(acc[r]);
            s[r] += __shfl_xor_sync(0xffffffffu, s[r], 1);
        }

        const long base = (long)c * 8 + khalf * 4;
#pragma unroll
        for (int r = 0; r < 4; ++r)
            out[(base + r) * HID + j] = s[khalf * 4 + r] + bias;

        if (has) *(float2*)&xs[p ^ 1][sdst] = nxt;
        __syncthreads();
        p ^= 1;
        c = cn;
    }
}

// ---------------------------------------------------------------------------
// Kernel 2: recurrent scan. 128 CTAs x 4 batch rows, 512 threads.
// Thread (j2, q): columns c0=j2, c1=j2+128; k in [64q, 64q+64).
// Weights: c0 k-first-half in 16 u64 REGISTERS; c0 second half + all of c1
// streamed from a per-thread smem row (96 floats, stride 100).
// Register budget deliberately ~100 (<128) so ptxas can software-pipeline.
// h in smem [b][272] (64+4 pad per chunk), double buffered, 1 barrier/step.
// 6-shfl recursive-halving reduce over the quad; lane q owns batch q.
// ---------------------------------------------------------------------------
#define WROW 100                       // 96 weights + 4 pad
#define HROW 272                       // 4 chunks of 68 per batch row

__device__ __forceinline__ int hpos(int c) {
    return (c >> 6) * 68 + (c & 63);
}

__global__ void __launch_bounds__(512, 1) rnn_scan_kernel(
    float* __restrict__ xo,
    const float* __restrict__ hidden0,
    const float* __restrict__ Whh,
    float* __restrict__ hlast)
{
    extern __shared__ float sm[];
    float* Wt   = sm;                  // [512][WROW]
    float* hbuf = sm + 512 * WROW;     // 2 x [4][HROW]

    const int t    = threadIdx.x;
    const int j2   = t >> 2;
    const int q    = t & 3;
    const int koff = q * 64;
    const int c0   = j2, c1 = j2 + 128;
    const int b0   = blockIdx.x * 4;

    // register weights: c0, k in [koff, koff+32)
    u64 WR[16];
#pragma unroll
    for (int k2 = 0; k2 < 16; ++k2)
        WR[k2] = pack2(Whh[(koff + 2 * k2) * HID + c0],
                       Whh[(koff + 2 * k2 + 1) * HID + c0]);
    // smem weights: [0..31] = c0 k in [koff+32, koff+64); [32..95] = c1 full quarter
    {
        float* wr = Wt + t * WROW;
        for (int i = 0; i < 32; ++i) wr[i]      = Whh[(koff + 32 + i) * HID + c0];
        for (int i = 0; i < 64; ++i) wr[32 + i] = Whh[(koff + i) * HID + c1];
    }

    for (int idx = t; idx < 4 * HID; idx += 512) {
        int b = idx >> 8, k = idx & 255;
        hbuf[b * HROW + hpos(k)] = hidden0[(b0 + b) * HID + k];
    }
    __syncthreads();

    const int p0 = hpos(c0), p1 = hpos(c1);
    float hold0 = hidden0[(b0 + q) * HID + c0];
    float hold1 = hidden0[(b0 + q) * HID + c1];
    float xp0   = xo[(long)(b0 + q) * HID + c0];
    float xp1   = xo[(long)(b0 + q) * HID + c1];

    const bool qb0 = (q & 1);          // lane bit0 / bit1 as bools
    const bool qb1 = (q & 2);

    int p = 0;
    for (int s = 0; s < SEQ; ++s) {
        float xn0, xn1;
        if (s + 1 < SEQ) {
            const long rb = ((long)(s + 1) * BATCH + b0 + q) * HID;
            xn0 = xo[rb + c0];
            xn1 = xo[rb + c1];
        }

        const float* hc   = hbuf + p * 4 * HROW;
        float*       hn   = hbuf + (p ^ 1) * 4 * HROW;
        const float* wrow = Wt + t * WROW;

        u64 aC0[4], aC1[4];
#pragma unroll
        for (int b = 0; b < 4; ++b) { aC0[b] = 0ull; aC1[b] = 0ull; }

#pragma unroll
        for (int k4 = 0; k4 < 16; ++k4) {
            ulonglong2 wc1 = *(const ulonglong2*)(wrow + 32 + 4 * k4);
            u64 w0lo, w0hi;
            if (k4 < 8) { w0lo = WR[2 * k4]; w0hi = WR[2 * k4 + 1]; }
            else {
                ulonglong2 w0 = *(const ulonglong2*)(wrow + (k4 - 8) * 4);
                w0lo = w0.x; w0hi = w0.y;
            }
#pragma unroll
            for (int b = 0; b < 4; ++b) {
                ulonglong2 h2 = *(const ulonglong2*)(hc + b * HROW + q * 68 + 4 * k4);
                aC0[b] = ffma2(w0lo, h2.x, aC0[b]);
                aC0[b] = ffma2(w0hi, h2.y, aC0[b]);
                aC1[b] = ffma2(wc1.x, h2.x, aC1[b]);
                aC1[b] = ffma2(wc1.y, h2.y, aC1[b]);
            }
        }

        // v[o], o = b*2 + c  (c: 0 -> c0, 1 -> c1); reduce over quad lanes,
        // recursive halving; lane q ends owning outputs (b=q, c0) and (b=q, c1).
        float v[8];
#pragma unroll
        for (int b = 0; b < 4; ++b) {
            v[2 * b + 0] = sum2(aC0[b]);
            v[2 * b + 1] = sum2(aC1[b]);
        }
        // round 1 (xor 1): keep outputs with (b & 1) == (q & 1)
        float u[4];
#pragma unroll
        for (int i = 0; i < 4; ++i) {
            // i = (b>>1)*2 + c ; kept b = (q&1) + 2*(i>>1)
            int  ok   = (2 * (qb0 ? 1 : 0) + 4 * (i >> 1)) + (i & 1);   // kept o
            int  os   = (2 * (qb0 ? 0 : 1) + 4 * (i >> 1)) + (i & 1);   // sent o
            float snd = v[os];
            float rcv = __shfl_xor_sync(0xffffffffu, snd, 1);
            u[i] = v[ok] + rcv;
        }
        // round 2 (xor 2): keep (b>>1) == (q>>1)  -> b == q
        float w0, w1;
        {
            float s0 = qb1 ? u[0] : u[2];
            float s1 = qb1 ? u[1] : u[3];
            float r0 = __shfl_xor_sync(0xffffffffu, s0, 2);
            float r1 = __shfl_xor_sync(0xffffffffu, s1, 2);
            w0 = (qb1 ? u[2] : u[0]) + r0;
            w1 = (qb1 ? u[3] : u[1]) + r1;
        }

        float v0 = 0.8f * hold0 + 0.2f * fmaxf(w0 + xp0, 0.f);
        float v1 = 0.8f * hold1 + 0.2f * fmaxf(w1 + xp1, 0.f);

        const long ob = ((long)s * BATCH + b0 + q) * HID;
        xo[ob + c0] = v0;
        xo[ob + c1] = v1;
        hn[q * HROW + p0] = v0;
        hn[q * HROW + p1] = v1;

        hold0 = v0; hold1 = v1;
        xp0 = xn0;  xp1 = xn1;

        __syncthreads();
        p ^= 1;
    }

    hlast[(long)(b0 + q) * HID + c0] = hold0;
    hlast[(long)(b0 + q) * HID + c1] = hold1;
}

// ---------------------------------------------------------------------------
extern "C" void kernel_launch(void* const* d_in, const int* in_sizes, int n_in,
                              void* d_out, int out_size) {
    const float* input  = (const float*)d_in[0];
    const float* hidden = (const float*)d_in[1];
    const float* Win    = (const float*)d_in[2];
    const float* b_in   = (const float*)d_in[3];
    const float* Whh    = (const float*)d_in[4];
    const float* b_hh   = (const float*)d_in[5];

    float* out   = (float*)d_out;                          // [SEQ,BATCH,HID]
    float* hlast = out + (long)SEQ * BATCH * HID;          // [BATCH,HID] tail

    xproj_kernel<<<148, 512>>>(input, Win, b_in, b_hh, out);

    const int smem = (512 * WROW + 2 * 4 * HROW) * (int)sizeof(float); // 213504 B
    cudaFuncSetAttribute(rnn_scan_kernel,
                         cudaFuncAttributeMaxDynamicSharedMemorySize, smem);
    rnn_scan_kernel<<<BATCH / 4, 512, smem>>>(out, hidden, Whh, hlast);
}

// round 14
// speedup vs baseline: 1.3591x; 1.3591x over previous
#include <cuda_runtime.h>
#include <cuda_bf16.h>
#include <cstdint>

#define SEQ   1024
#define BATCH 512
#define INF   128
#define HID   256

typedef unsigned long long u64;

// ---------------- f32x2 helpers (scan) --------------------------------------
__device__ __forceinline__ u64 pack2(float lo, float hi) {
    u64 r; asm("mov.b64 %0, {%1, %2};" : "=l"(r) : "f"(lo), "f"(hi)); return r;
}
__device__ __forceinline__ void unpack2(u64 v, float& lo, float& hi) {
    asm("mov.b64 {%0, %1}, %2;" : "=f"(lo), "=f"(hi) : "l"(v));
}
__device__ __forceinline__ u64 ffma2(u64 a, u64 b, u64 c) {
    u64 d; asm("fma.rn.f32x2 %0, %1, %2, %3;" : "=l"(d) : "l"(a), "l"(b), "l"(c));
    return d;
}
__device__ __forceinline__ float sum2(u64 v) {
    float lo, hi; unpack2(v, lo, hi); return lo + hi;
}
__device__ __forceinline__ float red4(float v) {
    v += __shfl_xor_sync(0xffffffffu, v, 1);
    v += __shfl_xor_sync(0xffffffffu, v, 2);
    return v;
}

// ---------------- HMMA helpers (base sm_103 ISA: sm_80+ features only) ------
__device__ __forceinline__ uint32_t s2u(const void* p) {
    uint32_t a;
    asm("{ .reg .u64 t; cvta.to.shared.u64 t, %1; cvt.u32.u64 %0, t; }"
        : "=r"(a) : "l"(p));
    return a;
}
#define CVTB(r, a, b) \
    asm("cvt.rn.satfinite.bf16x2.f32 %0, %1, %2;" : "=r"(r) : "f"(b), "f"(a))
// r: lo16 = bf16(a), hi16 = bf16(b)

#define LDSM_X4(r0, r1, r2, r3, addr) \
    asm volatile("ldmatrix.sync.aligned.m8n8.x4.shared.b16 {%0,%1,%2,%3}, [%4];" \
        : "=r"(r0), "=r"(r1), "=r"(r2), "=r"(r3) : "r"(addr))
#define LDSM_X4T(r0, r1, r2, r3, addr) \
    asm volatile("ldmatrix.sync.aligned.m8n8.x4.trans.shared.b16 {%0,%1,%2,%3}, [%4];" \
        : "=r"(r0), "=r"(r1), "=r"(r2), "=r"(r3) : "r"(addr))

#define MMA16816(c, a, b) \
    asm volatile("mma.sync.aligned.m16n8k16.row.col.f32.bf16.bf16.f32 " \
        "{%0,%1,%2,%3}, {%4,%5,%6,%7}, {%8,%9}, {%0,%1,%2,%3};" \
        : "+f"((c)[0]), "+f"((c)[1]), "+f"((c)[2]), "+f"((c)[3]) \
        : "r"((a)[0]), "r"((a)[1]), "r"((a)[2]), "r"((a)[3]), \
          "r"((b)[0]), "r"((b)[1]))

// ---------------- xproj via mma.sync bf16 split ------------------------------
// out = input @ Win + (b_in + b_hh); C = AhiWhi + AloWhi + AhiWlo.
// CTA tile 128x256; warp (wr,wc) computes rows [wr*32,+32) x cols [wc*128,+128).
#define ARX      136                      // A smem row stride (bf16): +4 banks/row
#define WRX      264                      // W smem row stride (bf16): +4 banks/row
#define XS_AHI   0
#define XS_ALO   34816                    // 128*136*2
#define XS_WHI   69632
#define XS_WLO   137216                   // + 128*264*2
#define XS_TOT   204800
#define AOFFB    (XS_ALO - XS_AHI)
#define WOFFB    (XS_WLO - XS_WHI)
#define NTILES   ((SEQ * BATCH) / 128)    // 4096

__global__ void __launch_bounds__(256, 1) xproj_hmma_kernel(
    const float* __restrict__ input, const float* __restrict__ Win,
    const float* __restrict__ b_in,  const float* __restrict__ b_hh,
    float* __restrict__ out)
{
    extern __shared__ char smx[];
    const uint32_t sb = s2u(smx);
    const int t = threadIdx.x, w = t >> 5, lane = t & 31;
    const int wr = w >> 1, wc = w & 1;          // 4 row-slabs x 2 col-halves
    const int g = lane >> 2, tig = lane & 3;

    // ---- W split -> smem (once) ----
    for (int idx = t; idx < INF * HID; idx += 256) {
        int k = idx >> 8, n = idx & 255;
        float wv = Win[idx];
        __nv_bfloat16 h = __float2bfloat16(wv);
        __nv_bfloat16 l = __float2bfloat16(wv - __bfloat162float(h));
        *(__nv_bfloat16*)(smx + XS_WHI + (k * WRX + n) * 2) = h;
        *(__nv_bfloat16*)(smx + XS_WLO + (k * WRX + n) * 2) = l;
    }

    // ---- bias kept in regs; folded into accumulator init ----
    float2 bias[16];
#pragma unroll
    for (int nt = 0; nt < 16; ++nt) {
        int col = wc * 128 + nt * 8 + tig * 2;
        bias[nt].x = b_in[col] + b_hh[col];
        bias[nt].y = b_in[col + 1] + b_hh[col + 1];
    }
    __syncthreads();

    // ---- precomputed addresses ----
    const int arow = t >> 1, akh = (t & 1) * 64;          // conversion mapping
    const int lr = lane & 15, lc = (lane >> 4) * 8;       // ldmatrix lane mapping
    uint32_t a_ld0 = sb + XS_AHI + ((wr * 32 + lr) * ARX + lc) * 2;       // mt=0
    uint32_t a_ld1 = sb + XS_AHI + ((wr * 32 + 16 + lr) * ARX + lc) * 2;  // mt=1
    uint32_t b_ld  = sb + XS_WHI + (lr * WRX + wc * 128 + lc) * 2;

    for (int tile = blockIdx.x; tile < NTILES; tile += gridDim.x) {
        __syncthreads();   // prev tile's ldmatrix (cross-warp rows) done

        // ---- load + split-convert A tile [128 x 128] ----
        const float4* ib = (const float4*)(input + (long)tile * (128 * INF)
                                           + arow * INF + akh);
#pragma unroll
        for (int i = 0; i < 16; ++i) {
            float4 v = ib[i];
            uint32_t h0; CVTB(h0, v.x, v.y);
            uint32_t h1; CVTB(h1, v.z, v.w);
            float r0 = __uint_as_float(h0 << 16);
            float r1 = __uint_as_float(h0 & 0xffff0000u);
            float r2 = __uint_as_float(h1 << 16);
            float r3 = __uint_as_float(h1 & 0xffff0000u);
            uint32_t l0; CVTB(l0, v.x - r0, v.y - r1);
            uint32_t l1; CVTB(l1, v.z - r2, v.w - r3);
            uint32_t off = (uint32_t)(arow * ARX + akh + i * 4) * 2;
            *(uint2*)(smx + XS_AHI + off) = make_uint2(h0, h1);
            *(uint2*)(smx + XS_ALO + off) = make_uint2(l0, l1);
        }
        __syncthreads();

        // ---- accumulators, bias-initialized ----
        float acc[2][16][4];
#pragma unroll
        for (int mt = 0; mt < 2; ++mt)
#pragma unroll
            for (int nt = 0; nt < 16; ++nt) {
                acc[mt][nt][0] = bias[nt].x; acc[mt][nt][1] = bias[nt].y;
                acc[mt][nt][2] = bias[nt].x; acc[mt][nt][3] = bias[nt].y;
            }

        // ---- K loop: 8 steps of k16; 3 passes fused per step ----
#pragma unroll
        for (int ks = 0; ks < 8; ++ks) {
            uint32_t ah0[4], ah1[4], al0[4], al1[4];
            LDSM_X4(ah0[0], ah0[1], ah0[2], ah0[3], a_ld0 + ks * 32);
            LDSM_X4(ah1[0], ah1[1], ah1[2], ah1[3], a_ld1 + ks * 32);
            LDSM_X4(al0[0], al0[1], al0[2], al0[3], a_ld0 + AOFFB + ks * 32);
            LDSM_X4(al1[0], al1[1], al1[2], al1[3], a_ld1 + AOFFB + ks * 32);

#pragma unroll
            for (int half = 0; half < 2; ++half) {
                uint32_t bh[8][2], bl[8][2];
#pragma unroll
                for (int i = 0; i < 4; ++i) {
                    uint32_t ba = b_ld + (uint32_t)ks * (16 * WRX * 2)
                                + (half * 4 + i) * 32;
                    LDSM_X4T(bh[2 * i][0], bh[2 * i][1],
                             bh[2 * i + 1][0], bh[2 * i + 1][1], ba);
                    LDSM_X4T(bl[2 * i][0], bl[2 * i][1],
                             bl[2 * i + 1][0], bl[2 * i + 1][1], ba + WOFFB);
                }
#pragma unroll
                for (int i = 0; i < 8; ++i) {
                    int nt = half * 8 + i;
                    MMA16816(acc[0][nt], ah0, bh[i]);
                    MMA16816(acc[1][nt], ah1, bh[i]);
                    MMA16816(acc[0][nt], al0, bh[i]);
                    MMA16816(acc[1][nt], al1, bh[i]);
                    MMA16816(acc[0][nt], ah0, bl[i]);
                    MMA16816(acc[1][nt], ah1, bl[i]);
                }
            }
        }

        // ---- epilogue: direct global stores (c-frag layout) ----
#pragma unroll
        for (int mt = 0; mt < 2; ++mt) {
            const long rbase = (long)(tile * 128 + wr * 32 + mt * 16 + g);
#pragma unroll
            for (int nt = 0; nt < 16; ++nt) {
                int col = wc * 128 + nt * 8 + tig * 2;
                *(float2*)(out + rbase * HID + col) =
                    make_float2(acc[mt][nt][0], acc[mt][nt][1]);
                *(float2*)(out + (rbase + 8) * HID + col) =
                    make_float2(acc[mt][nt][2], acc[mt][nt][3]);
            }
        }
    }
}

// ---------------- recurrent scan (R8, best known: unchanged) ----------------
#define WROW 68
#define HROW 272

__device__ __forceinline__ int hpos(int c) {
    return (c >> 6) * 68 + (c & 63);
}

__global__ void __launch_bounds__(512, 1) rnn_scan_kernel(
    float* __restrict__ xo,
    const float* __restrict__ hidden0,
    const float* __restrict__ Whh,
    float* __restrict__ hlast)
{
    extern __shared__ float sm[];
    float* Wt   = sm;                  // [512][WROW]
    float* hbuf = sm + 512 * WROW;     // 2 x [4][HROW]

    const int t    = threadIdx.x;
    const int j2   = t >> 2;
    const int q    = t & 3;
    const int koff = q * 64;
    const int c0   = j2, c1 = j2 + 128;
    const int cr   = (q & 1) ? c1 : c0;
    const int cs   = (q & 1) ? c0 : c1;
    const int b0   = blockIdx.x * 4;
    const int myb  = q;

    u64 WR[32];
#pragma unroll
    for (int k2 = 0; k2 < 32; ++k2)
        WR[k2] = pack2(Whh[(koff + 2 * k2) * HID + cr],
                       Whh[(koff + 2 * k2 + 1) * HID + cr]);
    for (int i = 0; i < 64; ++i)
        Wt[t * WROW + i] = Whh[(koff + i) * HID + cs];

    for (int idx = t; idx < 4 * HID; idx += 512) {
        int b = idx >> 8, k = idx & 255;
        hbuf[b * HROW + hpos(k)] = hidden0[(b0 + b) * HID + k];
    }
    __syncthreads();

    const int p0 = hpos(c0), p1 = hpos(c1);
    float hold0 = hidden0[(b0 + myb) * HID + c0];
    float hold1 = hidden0[(b0 + myb) * HID + c1];

    float xp0 = xo[(long)(b0 + myb) * HID + c0];
    float xp1 = xo[(long)(b0 + myb) * HID + c1];

    int p = 0;
    for (int s = 0; s < SEQ; ++s) {
        float xn0, xn1;
        if (s + 1 < SEQ) {
            const long rb = ((long)(s + 1) * BATCH + b0 + myb) * HID;
            xn0 = xo[rb + c0];
            xn1 = xo[rb + c1];
        }

        const float* hc = hbuf + p * 4 * HROW;
        float*       hn = hbuf + (p ^ 1) * 4 * HROW;

        u64 aR[4], aS[4];
#pragma unroll
        for (int b = 0; b < 4; ++b) { aR[b] = 0ull; aS[b] = 0ull; }

        const float* wrow = Wt + t * WROW;
#pragma unroll
        for (int k4 = 0; k4 < 16; ++k4) {
            ulonglong2 w2 = *(const ulonglong2*)(wrow + 4 * k4);
#pragma unroll
            for (int b = 0; b < 4; ++b) {
                ulonglong2 h2 = *(const ulonglong2*)(hc + b * HROW + q * 68 + 4 * k4);
                aR[b] = ffma2(WR[2 * k4 + 0], h2.x, aR[b]);
                aR[b] = ffma2(WR[2 * k4 + 1], h2.y, aR[b]);
                aS[b] = ffma2(w2.x, h2.x, aS[b]);
                aS[b] = ffma2(w2.y, h2.y, aS[b]);
            }
        }

        float s00, s01, s02, s03, s10, s11, s12, s13;
        {
            const bool sw = (q & 1);
            s00 = red4(sw ? sum2(aS[0]) : sum2(aR[0]));
            s01 = red4(sw ? sum2(aS[1]) : sum2(aR[1]));
            s02 = red4(sw ? sum2(aS[2]) : sum2(aR[2]));
            s03 = red4(sw ? sum2(aS[3]) : sum2(aR[3]));
            s10 = red4(sw ? sum2(aR[0]) : sum2(aS[0]));
            s11 = red4(sw ? sum2(aR[1]) : sum2(aS[1]));
            s12 = red4(sw ? sum2(aR[2]) : sum2(aS[2]));
            s13 = red4(sw ? sum2(aR[3]) : sum2(aS[3]));
        }
        float pc0 = (q == 0) ? s00 : (q == 1) ? s01 : (q == 2) ? s02 : s03;
        float pc1 = (q == 0) ? s10 : (q == 1) ? s11 : (q == 2) ? s12 : s13;

        float v0 = 0.8f * hold0 + 0.2f * fmaxf(pc0 + xp0, 0.f);
        float v1 = 0.8f * hold1 + 0.2f * fmaxf(pc1 + xp1, 0.f);

        const long ob = ((long)s * BATCH + b0 + myb) * HID;
        xo[ob + c0] = v0;
        xo[ob + c1] = v1;
        hn[myb * HROW + p0] = v0;
        hn[myb * HROW + p1] = v1;

        hold0 = v0; hold1 = v1;
        xp0 = xn0;  xp1 = xn1;

        __syncthreads();
        p ^= 1;
    }

    hlast[(long)(b0 + myb) * HID + c0] = hold0;
    hlast[(long)(b0 + myb) * HID + c1] = hold1;
}

// ---------------------------------------------------------------------------
extern "C" void kernel_launch(void* const* d_in, const int* in_sizes, int n_in,
                              void* d_out, int out_size) {
    const float* input  = (const float*)d_in[0];
    const float* hidden = (const float*)d_in[1];
    const float* Win    = (const float*)d_in[2];
    const float* b_in   = (const float*)d_in[3];
    const float* Whh    = (const float*)d_in[4];
    const float* b_hh   = (const float*)d_in[5];

    float* out   = (float*)d_out;                          // [SEQ,BATCH,HID]
    float* hlast = out + (long)SEQ * BATCH * HID;          // [BATCH,HID] tail

    cudaFuncSetAttribute(xproj_hmma_kernel,
                         cudaFuncAttributeMaxDynamicSharedMemorySize, XS_TOT);
    xproj_hmma_kernel<<<148, 256, XS_TOT>>>(input, Win, b_in, b_hh, out);

    const int smem = (512 * WROW + 2 * 4 * HROW) * (int)sizeof(float); // 147968 B
    cudaFuncSetAttribute(rnn_scan_kernel,
                         cudaFuncAttributeMaxDynamicSharedMemorySize, smem);
    rnn_scan_kernel<<<BATCH / 4, 512, smem>>>(out, hidden, Whh, hlast);
}

// round 15
// speedup vs baseline: 1.3830x; 1.0175x over previous
#include <cuda_runtime.h>
#include <cuda_bf16.h>
#include <cstdint>

#define SEQ   1024
#define BATCH 512
#define INF   128
#define HID   256

// ---------------- HMMA helpers (base sm_103 ISA) -----------------------------
__device__ __forceinline__ uint32_t s2u(const void* p) {
    uint32_t a;
    asm("{ .reg .u64 t; cvta.to.shared.u64 t, %1; cvt.u32.u64 %0, t; }"
        : "=r"(a) : "l"(p));
    return a;
}
#define CVTB(r, a, b) \
    asm("cvt.rn.satfinite.bf16x2.f32 %0, %1, %2;" : "=r"(r) : "f"(b), "f"(a))
// r: lo16 = bf16(a), hi16 = bf16(b)

#define LDSM_X4(r0, r1, r2, r3, addr) \
    asm volatile("ldmatrix.sync.aligned.m8n8.x4.shared.b16 {%0,%1,%2,%3}, [%4];" \
        : "=r"(r0), "=r"(r1), "=r"(r2), "=r"(r3) : "r"(addr))
#define LDSM_X4T(r0, r1, r2, r3, addr) \
    asm volatile("ldmatrix.sync.aligned.m8n8.x4.trans.shared.b16 {%0,%1,%2,%3}, [%4];" \
        : "=r"(r0), "=r"(r1), "=r"(r2), "=r"(r3) : "r"(addr))

#define MMA16816(c, a, b) \
    asm volatile("mma.sync.aligned.m16n8k16.row.col.f32.bf16.bf16.f32 " \
        "{%0,%1,%2,%3}, {%4,%5,%6,%7}, {%8,%9}, {%0,%1,%2,%3};" \
        : "+f"((c)[0]), "+f"((c)[1]), "+f"((c)[2]), "+f"((c)[3]) \
        : "r"((a)[0]), "r"((a)[1]), "r"((a)[2]), "r"((a)[3]), \
          "r"((b)[0]), "r"((b)[1]))

// ---------------- xproj via mma.sync bf16 split (R14, unchanged) -------------
#define ARX      136
#define WRX      264
#define XS_AHI   0
#define XS_ALO   34816
#define XS_WHI   69632
#define XS_WLO   137216
#define XS_TOT   204800
#define AOFFB    (XS_ALO - XS_AHI)
#define WOFFB    (XS_WLO - XS_WHI)
#define NTILES   ((SEQ * BATCH) / 128)

__global__ void __launch_bounds__(256, 1) xproj_hmma_kernel(
    const float* __restrict__ input, const float* __restrict__ Win,
    const float* __restrict__ b_in,  const float* __restrict__ b_hh,
    float* __restrict__ out)
{
    extern __shared__ char smx[];
    const uint32_t sb = s2u(smx);
    const int t = threadIdx.x, w = t >> 5, lane = t & 31;
    const int wr = w >> 1, wc = w & 1;
    const int g = lane >> 2, tig = lane & 3;

    for (int idx = t; idx < INF * HID; idx += 256) {
        int k = idx >> 8, n = idx & 255;
        float wv = Win[idx];
        __nv_bfloat16 h = __float2bfloat16(wv);
        __nv_bfloat16 l = __float2bfloat16(wv - __bfloat162float(h));
        *(__nv_bfloat16*)(smx + XS_WHI + (k * WRX + n) * 2) = h;
        *(__nv_bfloat16*)(smx + XS_WLO + (k * WRX + n) * 2) = l;
    }

    float2 bias[16];
#pragma unroll
    for (int nt = 0; nt < 16; ++nt) {
        int col = wc * 128 + nt * 8 + tig * 2;
        bias[nt].x = b_in[col] + b_hh[col];
        bias[nt].y = b_in[col + 1] + b_hh[col + 1];
    }
    __syncthreads();

    const int arow = t >> 1, akh = (t & 1) * 64;
    const int lr = lane & 15, lc = (lane >> 4) * 8;
    uint32_t a_ld0 = sb + XS_AHI + ((wr * 32 + lr) * ARX + lc) * 2;
    uint32_t a_ld1 = sb + XS_AHI + ((wr * 32 + 16 + lr) * ARX + lc) * 2;
    uint32_t b_ld  = sb + XS_WHI + (lr * WRX + wc * 128 + lc) * 2;

    for (int tile = blockIdx.x; tile < NTILES; tile += gridDim.x) {
        __syncthreads();

        const float4* ib = (const float4*)(input + (long)tile * (128 * INF)
                                           + arow * INF + akh);
#pragma unroll
        for (int i = 0; i < 16; ++i) {
            float4 v = ib[i];
            uint32_t h0; CVTB(h0, v.x, v.y);
            uint32_t h1; CVTB(h1, v.z, v.w);
            float r0 = __uint_as_float(h0 << 16);
            float r1 = __uint_as_float(h0 & 0xffff0000u);
            float r2 = __uint_as_float(h1 << 16);
            float r3 = __uint_as_float(h1 & 0xffff0000u);
            uint32_t l0; CVTB(l0, v.x - r0, v.y - r1);
            uint32_t l1; CVTB(l1, v.z - r2, v.w - r3);
            uint32_t off = (uint32_t)(arow * ARX + akh + i * 4) * 2;
            *(uint2*)(smx + XS_AHI + off) = make_uint2(h0, h1);
            *(uint2*)(smx + XS_ALO + off) = make_uint2(l0, l1);
        }
        __syncthreads();

        float acc[2][16][4];
#pragma unroll
        for (int mt = 0; mt < 2; ++mt)
#pragma unroll
            for (int nt = 0; nt < 16; ++nt) {
                acc[mt][nt][0] = bias[nt].x; acc[mt][nt][1] = bias[nt].y;
                acc[mt][nt][2] = bias[nt].x; acc[mt][nt][3] = bias[nt].y;
            }

#pragma unroll
        for (int ks = 0; ks < 8; ++ks) {
            uint32_t ah0[4], ah1[4], al0[4], al1[4];
            LDSM_X4(ah0[0], ah0[1], ah0[2], ah0[3], a_ld0 + ks * 32);
            LDSM_X4(ah1[0], ah1[1], ah1[2], ah1[3], a_ld1 + ks * 32);
            LDSM_X4(al0[0], al0[1], al0[2], al0[3], a_ld0 + AOFFB + ks * 32);
            LDSM_X4(al1[0], al1[1], al1[2], al1[3], a_ld1 + AOFFB + ks * 32);

#pragma unroll
            for (int half = 0; half < 2; ++half) {
                uint32_t bh[8][2], bl[8][2];
#pragma unroll
                for (int i = 0; i < 4; ++i) {
                    uint32_t ba = b_ld + (uint32_t)ks * (16 * WRX * 2)
                                + (half * 4 + i) * 32;
                    LDSM_X4T(bh[2 * i][0], bh[2 * i][1],
                             bh[2 * i + 1][0], bh[2 * i + 1][1], ba);
                    LDSM_X4T(bl[2 * i][0], bl[2 * i][1],
                             bl[2 * i + 1][0], bl[2 * i + 1][1], ba + WOFFB);
                }
#pragma unroll
                for (int i = 0; i < 8; ++i) {
                    int nt = half * 8 + i;
                    MMA16816(acc[0][nt], ah0, bh[i]);
                    MMA16816(acc[1][nt], ah1, bh[i]);
                    MMA16816(acc[0][nt], al0, bh[i]);
                    MMA16816(acc[1][nt], al1, bh[i]);
                    MMA16816(acc[0][nt], ah0, bl[i]);
                    MMA16816(acc[1][nt], ah1, bl[i]);
                }
            }
        }

#pragma unroll
        for (int mt = 0; mt < 2; ++mt) {
            const long rbase = (long)(tile * 128 + wr * 32 + mt * 16 + g);
#pragma unroll
            for (int nt = 0; nt < 16; ++nt) {
                int col = wc * 128 + nt * 8 + tig * 2;
                *(float2*)(out + rbase * HID + col) =
                    make_float2(acc[mt][nt][0], acc[mt][nt][1]);
                *(float2*)(out + (rbase + 8) * HID + col) =
                    make_float2(acc[mt][nt][2], acc[mt][nt][3]);
            }
        }
    }
}

// ---------------- HMMA recurrent scan ----------------------------------------
// 32 CTAs x 16 batch rows, 256 threads (8 warps). Warp w owns cols [w*32,+32).
// Whi fragments resident in regs (built once); Wlo streamed from smem.
// h double-buffered in smem as bf16 hi/lo; 1 barrier/step.
// pre = AhiWhi + AloWhi + AhiWlo (+xp, as accH init); h = .8h + .2relu(pre).
#define SCTA    16
#define WRX2    264
#define ARX2    264
#define SW_OFF  0
#define SW_BYTES (256 * WRX2 * 2)            // 135168
#define SA_OFF  SW_BYTES
#define SA_LO   8448                          // lo plane offset within buffer
#define SA_BUF  16896                         // hi+lo per buffer
#define S_TOTAL (SW_BYTES + 2 * SA_BUF)       // 168960

__global__ void __launch_bounds__(256, 1) rnn_scan_hmma(
    float* __restrict__ xo,            // d_out: xp in, h out (same locations)
    const float* __restrict__ hidden0,
    const float* __restrict__ Whh,
    float* __restrict__ hlast)
{
    extern __shared__ char smem[];
    const uint32_t sb = s2u(smem);
    const int t = threadIdx.x, w = t >> 5, lane = t & 31;
    const int g = lane >> 2, tig = lane & 3;
    const int b0 = blockIdx.x * SCTA;
    const int colw = w * 32;
    const int lr = lane & 15, lc = (lane >> 4) * 8;

    // phase 1: Whi -> smem, build resident fragments
    for (int idx = t; idx < HID * HID; idx += 256) {
        int k = idx >> 8, n = idx & 255;
        *(__nv_bfloat16*)(smem + SW_OFF + (k * WRX2 + n) * 2) =
            __float2bfloat16(Whh[idx]);
    }
    __syncthreads();

    uint32_t WH[16][4][2];
    {
        uint32_t base = sb + SW_OFF + (lr * WRX2 + colw + lc) * 2;
#pragma unroll
        for (int kt = 0; kt < 16; ++kt)
#pragma unroll
            for (int h = 0; h < 2; ++h) {
                uint32_t a = base + (uint32_t)kt * (16 * WRX2 * 2) + h * 32;
                LDSM_X4T(WH[kt][2 * h][0], WH[kt][2 * h][1],
                         WH[kt][2 * h + 1][0], WH[kt][2 * h + 1][1], a);
            }
    }
    __syncthreads();

    // phase 2: Wlo overwrites smem W; A(0) from hidden0; hold/xp init
    for (int idx = t; idx < HID * HID; idx += 256) {
        int k = idx >> 8, n = idx & 255;
        float wv = Whh[idx];
        __nv_bfloat16 h = __float2bfloat16(wv);
        *(__nv_bfloat16*)(smem + SW_OFF + (k * WRX2 + n) * 2) =
            __float2bfloat16(wv - __bfloat162float(h));
    }
    for (int idx = t; idx < SCTA * HID; idx += 256) {
        int r = idx >> 8, c = idx & 255;
        float hv = hidden0[(b0 + r) * HID + c];
        __nv_bfloat16 hb = __float2bfloat16(hv);
        *(__nv_bfloat16*)(smem + SA_OFF + (r * ARX2 + c) * 2) = hb;
        *(__nv_bfloat16*)(smem + SA_OFF + SA_LO + (r * ARX2 + c) * 2) =
            __float2bfloat16(hv - __bfloat162float(hb));
    }

    float hold[4][4], xpn[4][4];
#pragma unroll
    for (int nt = 0; nt < 4; ++nt) {
        int col = colw + nt * 8 + tig * 2;
        hold[nt][0] = hidden0[(b0 + g) * HID + col];
        hold[nt][1] = hidden0[(b0 + g) * HID + col + 1];
        hold[nt][2] = hidden0[(b0 + g + 8) * HID + col];
        hold[nt][3] = hidden0[(b0 + g + 8) * HID + col + 1];
        float2 v0 = *(const float2*)(xo + (long)(b0 + g) * HID + col);
        float2 v1 = *(const float2*)(xo + (long)(b0 + g + 8) * HID + col);
        xpn[nt][0] = v0.x; xpn[nt][1] = v0.y;
        xpn[nt][2] = v1.x; xpn[nt][3] = v1.y;
    }
    __syncthreads();

    const uint32_t wlo_base = sb + SW_OFF + (lr * WRX2 + colw + lc) * 2;

    int p = 0;
    for (int s = 0; s < SEQ; ++s) {
        float accH[4][4], accL1[4][4], accL2[4][4];
#pragma unroll
        for (int nt = 0; nt < 4; ++nt)
#pragma unroll
            for (int i = 0; i < 4; ++i) {
                accH[nt][i]  = xpn[nt][i];
                accL1[nt][i] = 0.f;
                accL2[nt][i] = 0.f;
            }

        if (s + 1 < SEQ) {
#pragma unroll
            for (int nt = 0; nt < 4; ++nt) {
                int col = colw + nt * 8 + tig * 2;
                float2 v0 = *(const float2*)(xo + ((long)(s + 1) * BATCH + b0 + g) * HID + col);
                float2 v1 = *(const float2*)(xo + ((long)(s + 1) * BATCH + b0 + g + 8) * HID + col);
                xpn[nt][0] = v0.x; xpn[nt][1] = v0.y;
                xpn[nt][2] = v1.x; xpn[nt][3] = v1.y;
            }
        }

        const uint32_t abase = sb + SA_OFF + p * SA_BUF + (lr * ARX2 + lc) * 2;
#pragma unroll
        for (int kt = 0; kt < 16; ++kt) {
            uint32_t ah[4], al[4], wl[4][2];
            LDSM_X4(ah[0], ah[1], ah[2], ah[3], abase + kt * 32);
            LDSM_X4(al[0], al[1], al[2], al[3], abase + SA_LO + kt * 32);
            {
                uint32_t ba = wlo_base + (uint32_t)kt * (16 * WRX2 * 2);
                LDSM_X4T(wl[0][0], wl[0][1], wl[1][0], wl[1][1], ba);
                LDSM_X4T(wl[2][0], wl[2][1], wl[3][0], wl[3][1], ba + 32);
            }
#pragma unroll
            for (int nt = 0; nt < 4; ++nt) {
                MMA16816(accH[nt],  ah, WH[kt][nt]);
                MMA16816(accL1[nt], al, WH[kt][nt]);
                MMA16816(accL2[nt], ah, wl[nt]);
            }
        }

        // epilogue
        const long orow0 = ((long)s * BATCH + b0 + g) * HID;
        const long orow1 = ((long)s * BATCH + b0 + g + 8) * HID;
        char* hdst = smem + SA_OFF + (p ^ 1) * SA_BUF;
#pragma unroll
        for (int nt = 0; nt < 4; ++nt) {
            int col = colw + nt * 8 + tig * 2;
            float p0 = accH[nt][0] + accL1[nt][0] + accL2[nt][0];
            float p1 = accH[nt][1] + accL1[nt][1] + accL2[nt][1];
            float p2 = accH[nt][2] + accL1[nt][2] + accL2[nt][2];
            float p3 = accH[nt][3] + accL1[nt][3] + accL2[nt][3];
            float v0 = 0.8f * hold[nt][0] + 0.2f * fmaxf(p0, 0.f);
            float v1 = 0.8f * hold[nt][1] + 0.2f * fmaxf(p1, 0.f);
            float v2 = 0.8f * hold[nt][2] + 0.2f * fmaxf(p2, 0.f);
            float v3 = 0.8f * hold[nt][3] + 0.2f * fmaxf(p3, 0.f);
            hold[nt][0] = v0; hold[nt][1] = v1;
            hold[nt][2] = v2; hold[nt][3] = v3;

            *(float2*)(xo + orow0 + col) = make_float2(v0, v1);
            *(float2*)(xo + orow1 + col) = make_float2(v2, v3);

            uint32_t h01; CVTB(h01, v0, v1);
            uint32_t h23; CVTB(h23, v2, v3);
            float f0 = __uint_as_float(h01 << 16);
            float f1 = __uint_as_float(h01 & 0xffff0000u);
            float f2 = __uint_as_float(h23 << 16);
            float f3 = __uint_as_float(h23 & 0xffff0000u);
            uint32_t l01; CVTB(l01, v0 - f0, v1 - f1);
            uint32_t l23; CVTB(l23, v2 - f2, v3 - f3);

            uint32_t o0 = (uint32_t)(g * ARX2 + col) * 2;
            uint32_t o1 = (uint32_t)((g + 8) * ARX2 + col) * 2;
            *(uint32_t*)(hdst + o0)          = h01;
            *(uint32_t*)(hdst + o1)          = h23;
            *(uint32_t*)(hdst + SA_LO + o0)  = l01;
            *(uint32_t*)(hdst + SA_LO + o1)  = l23;
        }

        __syncthreads();
        p ^= 1;
    }

#pragma unroll
    for (int nt = 0; nt < 4; ++nt) {
        int col = colw + nt * 8 + tig * 2;
        *(float2*)(hlast + (long)(b0 + g) * HID + col) =
            make_float2(hold[nt][0], hold[nt][1]);
        *(float2*)(hlast + (long)(b0 + g + 8) * HID + col) =
            make_float2(hold[nt][2], hold[nt][3]);
    }
}

// ---------------------------------------------------------------------------
extern "C" void kernel_launch(void* const* d_in, const int* in_sizes, int n_in,
                              void* d_out, int out_size) {
    const float* input  = (const float*)d_in[0];
    const float* hidden = (const float*)d_in[1];
    const float* Win    = (const float*)d_in[2];
    const float* b_in   = (const float*)d_in[3];
    const float* Whh    = (const float*)d_in[4];
    const float* b_hh   = (const float*)d_in[5];

    float* out   = (float*)d_out;                          // [SEQ,BATCH,HID]
    float* hlast = out + (long)SEQ * BATCH * HID;          // [BATCH,HID] tail

    cudaFuncSetAttribute(xproj_hmma_kernel,
                         cudaFuncAttributeMaxDynamicSharedMemorySize, XS_TOT);
    xproj_hmma_kernel<<<148, 256, XS_TOT>>>(input, Win, b_in, b_hh, out);

    cudaFuncSetAttribute(rnn_scan_hmma,
                         cudaFuncAttributeMaxDynamicSharedMemorySize, S_TOTAL);
    rnn_scan_hmma<<<BATCH / SCTA, 256, S_TOTAL>>>(out, hidden, Whh, hlast);
}

// round 16
// speedup vs baseline: 1.8281x; 1.3218x over previous
#include <cuda_runtime.h>
#include <cuda_bf16.h>
#include <cstdint>

#define SEQ   1024
#define BATCH 512
#define INF   128
#define HID   256

// ---------------- HMMA helpers (base sm_103 ISA) -----------------------------
__device__ __forceinline__ uint32_t s2u(const void* p) {
    uint32_t a;
    asm("{ .reg .u64 t; cvta.to.shared.u64 t, %1; cvt.u32.u64 %0, t; }"
        : "=r"(a) : "l"(p));
    return a;
}
#define CVTB(r, a, b) \
    asm("cvt.rn.satfinite.bf16x2.f32 %0, %1, %2;" : "=r"(r) : "f"(b), "f"(a))
// r: lo16 = bf16(a), hi16 = bf16(b)

#define LDSM_X4(r0, r1, r2, r3, addr) \
    asm volatile("ldmatrix.sync.aligned.m8n8.x4.shared.b16 {%0,%1,%2,%3}, [%4];" \
        : "=r"(r0), "=r"(r1), "=r"(r2), "=r"(r3) : "r"(addr))
#define LDSM_X4T(r0, r1, r2, r3, addr) \
    asm volatile("ldmatrix.sync.aligned.m8n8.x4.trans.shared.b16 {%0,%1,%2,%3}, [%4];" \
        : "=r"(r0), "=r"(r1), "=r"(r2), "=r"(r3) : "r"(addr))

#define MMA16816(c, a, b) \
    asm volatile("mma.sync.aligned.m16n8k16.row.col.f32.bf16.bf16.f32 " \
        "{%0,%1,%2,%3}, {%4,%5,%6,%7}, {%8,%9}, {%0,%1,%2,%3};" \
        : "+f"((c)[0]), "+f"((c)[1]), "+f"((c)[2]), "+f"((c)[3]) \
        : "r"((a)[0]), "r"((a)[1]), "r"((a)[2]), "r"((a)[3]), \
          "r"((b)[0]), "r"((b)[1]))

// ---------------- xproj via mma.sync bf16 split (R14, unchanged) -------------
#define ARX      136
#define WRX      264
#define XS_AHI   0
#define XS_ALO   34816
#define XS_WHI   69632
#define XS_WLO   137216
#define XS_TOT   204800
#define AOFFB    (XS_ALO - XS_AHI)
#define WOFFB    (XS_WLO - XS_WHI)
#define NTILES   ((SEQ * BATCH) / 128)

__global__ void __launch_bounds__(256, 1) xproj_hmma_kernel(
    const float* __restrict__ input, const float* __restrict__ Win,
    const float* __restrict__ b_in,  const float* __restrict__ b_hh,
    float* __restrict__ out)
{
    extern __shared__ char smx[];
    const uint32_t sb = s2u(smx);
    const int t = threadIdx.x, w = t >> 5, lane = t & 31;
    const int wr = w >> 1, wc = w & 1;
    const int g = lane >> 2, tig = lane & 3;

    for (int idx = t; idx < INF * HID; idx += 256) {
        int k = idx >> 8, n = idx & 255;
        float wv = Win[idx];
        __nv_bfloat16 h = __float2bfloat16(wv);
        __nv_bfloat16 l = __float2bfloat16(wv - __bfloat162float(h));
        *(__nv_bfloat16*)(smx + XS_WHI + (k * WRX + n) * 2) = h;
        *(__nv_bfloat16*)(smx + XS_WLO + (k * WRX + n) * 2) = l;
    }

    float2 bias[16];
#pragma unroll
    for (int nt = 0; nt < 16; ++nt) {
        int col = wc * 128 + nt * 8 + tig * 2;
        bias[nt].x = b_in[col] + b_hh[col];
        bias[nt].y = b_in[col + 1] + b_hh[col + 1];
    }
    __syncthreads();

    const int arow = t >> 1, akh = (t & 1) * 64;
    const int lr = lane & 15, lc = (lane >> 4) * 8;
    uint32_t a_ld0 = sb + XS_AHI + ((wr * 32 + lr) * ARX + lc) * 2;
    uint32_t a_ld1 = sb + XS_AHI + ((wr * 32 + 16 + lr) * ARX + lc) * 2;
    uint32_t b_ld  = sb + XS_WHI + (lr * WRX + wc * 128 + lc) * 2;

    for (int tile = blockIdx.x; tile < NTILES; tile += gridDim.x) {
        __syncthreads();

        const float4* ib = (const float4*)(input + (long)tile * (128 * INF)
                                           + arow * INF + akh);
#pragma unroll
        for (int i = 0; i < 16; ++i) {
            float4 v = ib[i];
            uint32_t h0; CVTB(h0, v.x, v.y);
            uint32_t h1; CVTB(h1, v.z, v.w);
            float r0 = __uint_as_float(h0 << 16);
            float r1 = __uint_as_float(h0 & 0xffff0000u);
            float r2 = __uint_as_float(h1 << 16);
            float r3 = __uint_as_float(h1 & 0xffff0000u);
            uint32_t l0; CVTB(l0, v.x - r0, v.y - r1);
            uint32_t l1; CVTB(l1, v.z - r2, v.w - r3);
            uint32_t off = (uint32_t)(arow * ARX + akh + i * 4) * 2;
            *(uint2*)(smx + XS_AHI + off) = make_uint2(h0, h1);
            *(uint2*)(smx + XS_ALO + off) = make_uint2(l0, l1);
        }
        __syncthreads();

        float acc[2][16][4];
#pragma unroll
        for (int mt = 0; mt < 2; ++mt)
#pragma unroll
            for (int nt = 0; nt < 16; ++nt) {
                acc[mt][nt][0] = bias[nt].x; acc[mt][nt][1] = bias[nt].y;
                acc[mt][nt][2] = bias[nt].x; acc[mt][nt][3] = bias[nt].y;
            }

#pragma unroll
        for (int ks = 0; ks < 8; ++ks) {
            uint32_t ah0[4], ah1[4], al0[4], al1[4];
            LDSM_X4(ah0[0], ah0[1], ah0[2], ah0[3], a_ld0 + ks * 32);
            LDSM_X4(ah1[0], ah1[1], ah1[2], ah1[3], a_ld1 + ks * 32);
            LDSM_X4(al0[0], al0[1], al0[2], al0[3], a_ld0 + AOFFB + ks * 32);
            LDSM_X4(al1[0], al1[1], al1[2], al1[3], a_ld1 + AOFFB + ks * 32);

#pragma unroll
            for (int half = 0; half < 2; ++half) {
                uint32_t bh[8][2], bl[8][2];
#pragma unroll
                for (int i = 0; i < 4; ++i) {
                    uint32_t ba = b_ld + (uint32_t)ks * (16 * WRX * 2)
                                + (half * 4 + i) * 32;
                    LDSM_X4T(bh[2 * i][0], bh[2 * i][1],
                             bh[2 * i + 1][0], bh[2 * i + 1][1], ba);
                    LDSM_X4T(bl[2 * i][0], bl[2 * i][1],
                             bl[2 * i + 1][0], bl[2 * i + 1][1], ba + WOFFB);
                }
#pragma unroll
                for (int i = 0; i < 8; ++i) {
                    int nt = half * 8 + i;
                    MMA16816(acc[0][nt], ah0, bh[i]);
                    MMA16816(acc[1][nt], ah1, bh[i]);
                    MMA16816(acc[0][nt], al0, bh[i]);
                    MMA16816(acc[1][nt], al1, bh[i]);
                    MMA16816(acc[0][nt], ah0, bl[i]);
                    MMA16816(acc[1][nt], ah1, bl[i]);
                }
            }
        }

#pragma unroll
        for (int mt = 0; mt < 2; ++mt) {
            const long rbase = (long)(tile * 128 + wr * 32 + mt * 16 + g);
#pragma unroll
            for (int nt = 0; nt < 16; ++nt) {
                int col = wc * 128 + nt * 8 + tig * 2;
                *(float2*)(out + rbase * HID + col) =
                    make_float2(acc[mt][nt][0], acc[mt][nt][1]);
                *(float2*)(out + (rbase + 8) * HID + col) =
                    make_float2(acc[mt][nt][2], acc[mt][nt][3]);
            }
        }
    }
}

// ---------------- HMMA recurrent scan, 2-CTA cluster over N ------------------
// 32 clusters x 2 CTAs = 64 blocks. Cluster owns 16 batch rows; CTA r owns
// h columns [128r, +128). Warp w: 16 cols. Whi AND Wlo fragments register-
// resident. h (bf16 hi/lo, all 256 k-cols) double-buffered per CTA; each CTA
// writes its 128 h_new cols to own + peer buffer (DSMEM), barrier.cluster/step.
#define SCTA    16
#define WSTG    136                          // W staging row stride (bf16)
#define ARX2    264                          // h row stride (bf16)
#define SA_OFF  69632                        // after W staging (256*136*2)
#define SA_LO   8448                         // lo plane offset within buffer
#define SA_BUF  16896                        // hi+lo per buffer
#define S_TOTAL (SA_OFF + 2 * SA_BUF)        // 103424

__global__ void __launch_bounds__(256, 1) __cluster_dims__(2, 1, 1)
rnn_scan_hmma2(float* __restrict__ xo,
               const float* __restrict__ hidden0,
               const float* __restrict__ Whh,
               float* __restrict__ hlast)
{
    extern __shared__ char smem[];
    const uint32_t sb = s2u(smem);
    const int t = threadIdx.x, w = t >> 5, lane = t & 31;
    const int g = lane >> 2, tig = lane & 3;
    const int lr = lane & 15, lc = (lane >> 4) * 8;

    uint32_t rank;
    asm("mov.u32 %0, %%cluster_ctarank;" : "=r"(rank));
    const int b0      = (blockIdx.x >> 1) * SCTA;
    const int colbase = (int)rank * 128;
    const int colw_l  = w * 16;              // warp's first col (CTA-local)
    const int colw_g  = colbase + colw_l;    // global

    // ---- phase 1: Whi (this CTA's 128 cols) -> staging -> resident frags ----
    for (int idx = t; idx < HID * 128; idx += 256) {
        int k = idx >> 7, n = idx & 127;
        *(__nv_bfloat16*)(smem + (k * WSTG + n) * 2) =
            __float2bfloat16(Whh[k * HID + colbase + n]);
    }
    __syncthreads();
    uint32_t WH[16][2][2];
    {
        uint32_t base = sb + (lr * WSTG + colw_l + lc) * 2;
#pragma unroll
        for (int kt = 0; kt < 16; ++kt)
            LDSM_X4T(WH[kt][0][0], WH[kt][0][1], WH[kt][1][0], WH[kt][1][1],
                     base + (uint32_t)kt * (16 * WSTG * 2));
    }
    __syncthreads();

    // ---- phase 2: Wlo -> staging -> resident frags ----
    for (int idx = t; idx < HID * 128; idx += 256) {
        int k = idx >> 7, n = idx & 127;
        float wv = Whh[k * HID + colbase + n];
        __nv_bfloat16 h = __float2bfloat16(wv);
        *(__nv_bfloat16*)(smem + (k * WSTG + n) * 2) =
            __float2bfloat16(wv - __bfloat162float(h));
    }
    __syncthreads();
    uint32_t WL[16][2][2];
    {
        uint32_t base = sb + (lr * WSTG + colw_l + lc) * 2;
#pragma unroll
        for (int kt = 0; kt < 16; ++kt)
            LDSM_X4T(WL[kt][0][0], WL[kt][0][1], WL[kt][1][0], WL[kt][1][1],
                     base + (uint32_t)kt * (16 * WSTG * 2));
    }

    // ---- h(0): full 256 k-cols, hi/lo, buffer 0 ----
    for (int idx = t; idx < SCTA * HID; idx += 256) {
        int r = idx >> 8, c = idx & 255;
        float hv = hidden0[(b0 + r) * HID + c];
        __nv_bfloat16 hb = __float2bfloat16(hv);
        *(__nv_bfloat16*)(smem + SA_OFF + (r * ARX2 + c) * 2) = hb;
        *(__nv_bfloat16*)(smem + SA_OFF + SA_LO + (r * ARX2 + c) * 2) =
            __float2bfloat16(hv - __bfloat162float(hb));
    }

    // ---- hold / xp init for this thread's 8 outputs ----
    float hold[2][4], xpn[2][4];
#pragma unroll
    for (int nt = 0; nt < 2; ++nt) {
        int col = colw_g + nt * 8 + tig * 2;
        hold[nt][0] = hidden0[(b0 + g) * HID + col];
        hold[nt][1] = hidden0[(b0 + g) * HID + col + 1];
        hold[nt][2] = hidden0[(b0 + g + 8) * HID + col];
        hold[nt][3] = hidden0[(b0 + g + 8) * HID + col + 1];
        float2 v0 = *(const float2*)(xo + (long)(b0 + g) * HID + col);
        float2 v1 = *(const float2*)(xo + (long)(b0 + g + 8) * HID + col);
        xpn[nt][0] = v0.x; xpn[nt][1] = v0.y;
        xpn[nt][2] = v1.x; xpn[nt][3] = v1.y;
    }

    uint32_t peer_sb;
    asm("mapa.shared::cluster.u32 %0, %1, %2;"
        : "=r"(peer_sb) : "r"(sb), "r"(rank ^ 1u));

    asm volatile("barrier.cluster.arrive.aligned;" ::: "memory");
    asm volatile("barrier.cluster.wait.aligned;" ::: "memory");

    int p = 0;
    for (int s = 0; s < SEQ; ++s) {
        float accH[2][4], accL[2][4];
#pragma unroll
        for (int nt = 0; nt < 2; ++nt)
#pragma unroll
            for (int i = 0; i < 4; ++i) {
                accH[nt][i] = xpn[nt][i];
                accL[nt][i] = 0.f;
            }

        if (s + 1 < SEQ) {
#pragma unroll
            for (int nt = 0; nt < 2; ++nt) {
                int col = colw_g + nt * 8 + tig * 2;
                float2 v0 = *(const float2*)(xo + ((long)(s + 1) * BATCH + b0 + g) * HID + col);
                float2 v1 = *(const float2*)(xo + ((long)(s + 1) * BATCH + b0 + g + 8) * HID + col);
                xpn[nt][0] = v0.x; xpn[nt][1] = v0.y;
                xpn[nt][2] = v1.x; xpn[nt][3] = v1.y;
            }
        }

        const uint32_t abase = sb + SA_OFF + p * SA_BUF + (lr * ARX2 + lc) * 2;
#pragma unroll
        for (int kt = 0; kt < 16; ++kt) {
            uint32_t ah[4], al[4];
            LDSM_X4(ah[0], ah[1], ah[2], ah[3], abase + kt * 32);
            LDSM_X4(al[0], al[1], al[2], al[3], abase + SA_LO + kt * 32);
#pragma unroll
            for (int nt = 0; nt < 2; ++nt) {
                MMA16816(accH[nt], ah, WH[kt][nt]);
                MMA16816(accL[nt], al, WH[kt][nt]);
                MMA16816(accL[nt], ah, WL[kt][nt]);
            }
        }

        // ---- epilogue: blend, store global, write h hi/lo to own + peer ----
        const long orow0 = ((long)s * BATCH + b0 + g) * HID;
        const long orow1 = ((long)s * BATCH + b0 + g + 8) * HID;
        const uint32_t dst_l = sb      + SA_OFF + (p ^ 1) * SA_BUF;
        const uint32_t dst_p = peer_sb + SA_OFF + (p ^ 1) * SA_BUF;
#pragma unroll
        for (int nt = 0; nt < 2; ++nt) {
            int col = colw_g + nt * 8 + tig * 2;
            float p0 = accH[nt][0] + accL[nt][0];
            float p1 = accH[nt][1] + accL[nt][1];
            float p2 = accH[nt][2] + accL[nt][2];
            float p3 = accH[nt][3] + accL[nt][3];
            float v0 = 0.8f * hold[nt][0] + 0.2f * fmaxf(p0, 0.f);
            float v1 = 0.8f * hold[nt][1] + 0.2f * fmaxf(p1, 0.f);
            float v2 = 0.8f * hold[nt][2] + 0.2f * fmaxf(p2, 0.f);
            float v3 = 0.8f * hold[nt][3] + 0.2f * fmaxf(p3, 0.f);
            hold[nt][0] = v0; hold[nt][1] = v1;
            hold[nt][2] = v2; hold[nt][3] = v3;

            *(float2*)(xo + orow0 + col) = make_float2(v0, v1);
            *(float2*)(xo + orow1 + col) = make_float2(v2, v3);

            uint32_t h01; CVTB(h01, v0, v1);
            uint32_t h23; CVTB(h23, v2, v3);
            float f0 = __uint_as_float(h01 << 16);
            float f1 = __uint_as_float(h01 & 0xffff0000u);
            float f2 = __uint_as_float(h23 << 16);
            float f3 = __uint_as_float(h23 & 0xffff0000u);
            uint32_t l01; CVTB(l01, v0 - f0, v1 - f1);
            uint32_t l23; CVTB(l23, v2 - f2, v3 - f3);

            const uint32_t o0 = (uint32_t)(g * ARX2 + col) * 2;
            const uint32_t o1 = (uint32_t)((g + 8) * ARX2 + col) * 2;
            *(uint32_t*)(smem + (dst_l - sb) + o0)         = h01;
            *(uint32_t*)(smem + (dst_l - sb) + o1)         = h23;
            *(uint32_t*)(smem + (dst_l - sb) + SA_LO + o0) = l01;
            *(uint32_t*)(smem + (dst_l - sb) + SA_LO + o1) = l23;
            asm volatile("st.shared::cluster.b32 [%0], %1;"
                         :: "r"(dst_p + o0), "r"(h01) : "memory");
            asm volatile("st.shared::cluster.b32 [%0], %1;"
                         :: "r"(dst_p + o1), "r"(h23) : "memory");
            asm volatile("st.shared::cluster.b32 [%0], %1;"
                         :: "r"(dst_p + SA_LO + o0), "r"(l01) : "memory");
            asm volatile("st.shared::cluster.b32 [%0], %1;"
                         :: "r"(dst_p + SA_LO + o1), "r"(l23) : "memory");
        }

        asm volatile("barrier.cluster.arrive.aligned;" ::: "memory");
        asm volatile("barrier.cluster.wait.aligned;" ::: "memory");
        p ^= 1;
    }

#pragma unroll
    for (int nt = 0; nt < 2; ++nt) {
        int col = colw_g + nt * 8 + tig * 2;
        *(float2*)(hlast + (long)(b0 + g) * HID + col) =
            make_float2(hold[nt][0], hold[nt][1]);
        *(float2*)(hlast + (long)(b0 + g + 8) * HID + col) =
            make_float2(hold[nt][2], hold[nt][3]);
    }
}

// ---------------------------------------------------------------------------
extern "C" void kernel_launch(void* const* d_in, const int* in_sizes, int n_in,
                              void* d_out, int out_size) {
    const float* input  = (const float*)d_in[0];
    const float* hidden = (const float*)d_in[1];
    const float* Win    = (const float*)d_in[2];
    const float* b_in   = (const float*)d_in[3];
    const float* Whh    = (const float*)d_in[4];
    const float* b_hh   = (const float*)d_in[5];

    float* out   = (float*)d_out;                          // [SEQ,BATCH,HID]
    float* hlast = out + (long)SEQ * BATCH * HID;          // [BATCH,HID] tail

    cudaFuncSetAttribute(xproj_hmma_kernel,
                         cudaFuncAttributeMaxDynamicSharedMemorySize, XS_TOT);
    xproj_hmma_kernel<<<148, 256, XS_TOT>>>(input, Win, b_in, b_hh, out);

    cudaFuncSetAttribute(rnn_scan_hmma2,
                         cudaFuncAttributeMaxDynamicSharedMemorySize, S_TOTAL);
    rnn_scan_hmma2<<<(BATCH / SCTA) * 2, 256, S_TOTAL>>>(out, hidden, Whh, hlast);
}

// round 17
// speedup vs baseline: 1.8804x; 1.0286x over previous
#include <cuda_runtime.h>
#include <cuda_bf16.h>
#include <cstdint>

#define SEQ   1024
#define BATCH 512
#define INF   128
#define HID   256

// ---------------- HMMA helpers (base sm_103 ISA) -----------------------------
__device__ __forceinline__ uint32_t s2u(const void* p) {
    uint32_t a;
    asm("{ .reg .u64 t; cvta.to.shared.u64 t, %1; cvt.u32.u64 %0, t; }"
        : "=r"(a) : "l"(p));
    return a;
}
#define CVTB(r, a, b) \
    asm("cvt.rn.satfinite.bf16x2.f32 %0, %1, %2;" : "=r"(r) : "f"(b), "f"(a))
// r: lo16 = bf16(a), hi16 = bf16(b)

#define LDSM_X4(r0, r1, r2, r3, addr) \
    asm volatile("ldmatrix.sync.aligned.m8n8.x4.shared.b16 {%0,%1,%2,%3}, [%4];" \
        : "=r"(r0), "=r"(r1), "=r"(r2), "=r"(r3) : "r"(addr))
#define LDSM_X4T(r0, r1, r2, r3, addr) \
    asm volatile("ldmatrix.sync.aligned.m8n8.x4.trans.shared.b16 {%0,%1,%2,%3}, [%4];" \
        : "=r"(r0), "=r"(r1), "=r"(r2), "=r"(r3) : "r"(addr))
#define LDSM_X2T(r0, r1, addr) \
    asm volatile("ldmatrix.sync.aligned.m8n8.x2.trans.shared.b16 {%0,%1}, [%2];" \
        : "=r"(r0), "=r"(r1) : "r"(addr))

#define MMA16816(c, a, b) \
    asm volatile("mma.sync.aligned.m16n8k16.row.col.f32.bf16.bf16.f32 " \
        "{%0,%1,%2,%3}, {%4,%5,%6,%7}, {%8,%9}, {%0,%1,%2,%3};" \
        : "+f"((c)[0]), "+f"((c)[1]), "+f"((c)[2]), "+f"((c)[3]) \
        : "r"((a)[0]), "r"((a)[1]), "r"((a)[2]), "r"((a)[3]), \
          "r"((b)[0]), "r"((b)[1]))

// ---------------- xproj via mma.sync bf16 split (R14, unchanged) -------------
#define ARX      136
#define WRX      264
#define XS_AHI   0
#define XS_ALO   34816
#define XS_WHI   69632
#define XS_WLO   137216
#define XS_TOT   204800
#define AOFFB    (XS_ALO - XS_AHI)
#define WOFFB    (XS_WLO - XS_WHI)
#define NTILES   ((SEQ * BATCH) / 128)

__global__ void __launch_bounds__(256, 1) xproj_hmma_kernel(
    const float* __restrict__ input, const float* __restrict__ Win,
    const float* __restrict__ b_in,  const float* __restrict__ b_hh,
    float* __restrict__ out)
{
    extern __shared__ char smx[];
    const uint32_t sb = s2u(smx);
    const int t = threadIdx.x, w = t >> 5, lane = t & 31;
    const int wr = w >> 1, wc = w & 1;
    const int g = lane >> 2, tig = lane & 3;

    for (int idx = t; idx < INF * HID; idx += 256) {
        int k = idx >> 8, n = idx & 255;
        float wv = Win[idx];
        __nv_bfloat16 h = __float2bfloat16(wv);
        __nv_bfloat16 l = __float2bfloat16(wv - __bfloat162float(h));
        *(__nv_bfloat16*)(smx + XS_WHI + (k * WRX + n) * 2) = h;
        *(__nv_bfloat16*)(smx + XS_WLO + (k * WRX + n) * 2) = l;
    }

    float2 bias[16];
#pragma unroll
    for (int nt = 0; nt < 16; ++nt) {
        int col = wc * 128 + nt * 8 + tig * 2;
        bias[nt].x = b_in[col] + b_hh[col];
        bias[nt].y = b_in[col + 1] + b_hh[col + 1];
    }
    __syncthreads();

    const int arow = t >> 1, akh = (t & 1) * 64;
    const int lr = lane & 15, lc = (lane >> 4) * 8;
    uint32_t a_ld0 = sb + XS_AHI + ((wr * 32 + lr) * ARX + lc) * 2;
    uint32_t a_ld1 = sb + XS_AHI + ((wr * 32 + 16 + lr) * ARX + lc) * 2;
    uint32_t b_ld  = sb + XS_WHI + (lr * WRX + wc * 128 + lc) * 2;

    for (int tile = blockIdx.x; tile < NTILES; tile += gridDim.x) {
        __syncthreads();

        const float4* ib = (const float4*)(input + (long)tile * (128 * INF)
                                           + arow * INF + akh);
#pragma unroll
        for (int i = 0; i < 16; ++i) {
            float4 v = ib[i];
            uint32_t h0; CVTB(h0, v.x, v.y);
            uint32_t h1; CVTB(h1, v.z, v.w);
            float r0 = __uint_as_float(h0 << 16);
            float r1 = __uint_as_float(h0 & 0xffff0000u);
            float r2 = __uint_as_float(h1 << 16);
            float r3 = __uint_as_float(h1 & 0xffff0000u);
            uint32_t l0; CVTB(l0, v.x - r0, v.y - r1);
            uint32_t l1; CVTB(l1, v.z - r2, v.w - r3);
            uint32_t off = (uint32_t)(arow * ARX + akh + i * 4) * 2;
            *(uint2*)(smx + XS_AHI + off) = make_uint2(h0, h1);
            *(uint2*)(smx + XS_ALO + off) = make_uint2(l0, l1);
        }
        __syncthreads();

        float acc[2][16][4];
#pragma unroll
        for (int mt = 0; mt < 2; ++mt)
#pragma unroll
            for (int nt = 0; nt < 16; ++nt) {
                acc[mt][nt][0] = bias[nt].x; acc[mt][nt][1] = bias[nt].y;
                acc[mt][nt][2] = bias[nt].x; acc[mt][nt][3] = bias[nt].y;
            }

#pragma unroll
        for (int ks = 0; ks < 8; ++ks) {
            uint32_t ah0[4], ah1[4], al0[4], al1[4];
            LDSM_X4(ah0[0], ah0[1], ah0[2], ah0[3], a_ld0 + ks * 32);
            LDSM_X4(ah1[0], ah1[1], ah1[2], ah1[3], a_ld1 + ks * 32);
            LDSM_X4(al0[0], al0[1], al0[2], al0[3], a_ld0 + AOFFB + ks * 32);
            LDSM_X4(al1[0], al1[1], al1[2], al1[3], a_ld1 + AOFFB + ks * 32);

#pragma unroll
            for (int half = 0; half < 2; ++half) {
                uint32_t bh[8][2], bl[8][2];
#pragma unroll
                for (int i = 0; i < 4; ++i) {
                    uint32_t ba = b_ld + (uint32_t)ks * (16 * WRX * 2)
                                + (half * 4 + i) * 32;
                    LDSM_X4T(bh[2 * i][0], bh[2 * i][1],
                             bh[2 * i + 1][0], bh[2 * i + 1][1], ba);
                    LDSM_X4T(bl[2 * i][0], bl[2 * i][1],
                             bl[2 * i + 1][0], bl[2 * i + 1][1], ba + WOFFB);
                }
#pragma unroll
                for (int i = 0; i < 8; ++i) {
                    int nt = half * 8 + i;
                    MMA16816(acc[0][nt], ah0, bh[i]);
                    MMA16816(acc[1][nt], ah1, bh[i]);
                    MMA16816(acc[0][nt], al0, bh[i]);
                    MMA16816(acc[1][nt], al1, bh[i]);
                    MMA16816(acc[0][nt], ah0, bl[i]);
                    MMA16816(acc[1][nt], ah1, bl[i]);
                }
            }
        }

#pragma unroll
        for (int mt = 0; mt < 2; ++mt) {
            const long rbase = (long)(tile * 128 + wr * 32 + mt * 16 + g);
#pragma unroll
            for (int nt = 0; nt < 16; ++nt) {
                int col = wc * 128 + nt * 8 + tig * 2;
                *(float2*)(out + rbase * HID + col) =
                    make_float2(acc[mt][nt][0], acc[mt][nt][1]);
                *(float2*)(out + (rbase + 8) * HID + col) =
                    make_float2(acc[mt][nt][2], acc[mt][nt][3]);
            }
        }
    }
}

// ---------------- HMMA recurrent scan, 4-CTA cluster over N ------------------
// 32 clusters x 4 CTAs = 128 blocks. Cluster owns 16 batch rows; CTA r owns
// h columns [64r, +64). Warp w: 8 cols (1 n-tile). Whi+Wlo fragments register-
// resident. h (bf16 hi/lo, all 256 k-cols) double-buffered per CTA; each CTA
// writes its 64 h_new cols to own + 3 peers (DSMEM). barrier.cluster per step.
// Accumulator chains split by kt parity (6 sets, 8-deep chains).
#define SCTA    16
#define WSTG    72                           // W staging row stride (bf16)
#define ARX2    264                          // h row stride (bf16)
#define SA_OFF  36864                        // after W staging (256*72*2)
#define SA_LO   8448                         // lo plane offset within buffer
#define SA_BUF  16896                        // hi+lo per buffer
#define S_TOTAL (SA_OFF + 2 * SA_BUF)        // 70656

__global__ void __launch_bounds__(256, 1) __cluster_dims__(4, 1, 1)
rnn_scan_hmma4(float* __restrict__ xo,
               const float* __restrict__ hidden0,
               const float* __restrict__ Whh,
               float* __restrict__ hlast)
{
    extern __shared__ char smem[];
    const uint32_t sb = s2u(smem);
    const int t = threadIdx.x, w = t >> 5, lane = t & 31;
    const int g = lane >> 2, tig = lane & 3;
    const int lr = lane & 15;

    uint32_t rank;
    asm("mov.u32 %0, %%cluster_ctarank;" : "=r"(rank));
    const int b0      = (blockIdx.x >> 2) * SCTA;
    const int colbase = (int)rank * 64;
    const int colw_l  = w * 8;               // warp's 8 cols (CTA-local)
    const int colw_g  = colbase + colw_l;

    // ---- phase 1: Whi (this CTA's 64 cols) -> staging -> resident frags ----
    for (int idx = t; idx < HID * 64; idx += 256) {
        int k = idx >> 6, n = idx & 63;
        *(__nv_bfloat16*)(smem + (k * WSTG + n) * 2) =
            __float2bfloat16(Whh[k * HID + colbase + n]);
    }
    __syncthreads();
    uint32_t WH[16][2];
    {
#pragma unroll
        for (int kt = 0; kt < 16; ++kt) {
            uint32_t a = sb + (((uint32_t)(kt * 16 + lr)) * WSTG + colw_l) * 2;
            LDSM_X2T(WH[kt][0], WH[kt][1], a);
        }
    }
    __syncthreads();

    // ---- phase 2: Wlo -> staging -> resident frags ----
    for (int idx = t; idx < HID * 64; idx += 256) {
        int k = idx >> 6, n = idx & 63;
        float wv = Whh[k * HID + colbase + n];
        __nv_bfloat16 h = __float2bfloat16(wv);
        *(__nv_bfloat16*)(smem + (k * WSTG + n) * 2) =
            __float2bfloat16(wv - __bfloat162float(h));
    }
    __syncthreads();
    uint32_t WL[16][2];
    {
#pragma unroll
        for (int kt = 0; kt < 16; ++kt) {
            uint32_t a = sb + (((uint32_t)(kt * 16 + lr)) * WSTG + colw_l) * 2;
            LDSM_X2T(WL[kt][0], WL[kt][1], a);
        }
    }

    // ---- h(0): full 256 k-cols, hi/lo, buffer 0 ----
    for (int idx = t; idx < SCTA * HID; idx += 256) {
        int r = idx >> 8, c = idx & 255;
        float hv = hidden0[(b0 + r) * HID + c];
        __nv_bfloat16 hb = __float2bfloat16(hv);
        *(__nv_bfloat16*)(smem + SA_OFF + (r * ARX2 + c) * 2) = hb;
        *(__nv_bfloat16*)(smem + SA_OFF + SA_LO + (r * ARX2 + c) * 2) =
            __float2bfloat16(hv - __bfloat162float(hb));
    }

    // ---- hold / xp init for this thread's 4 outputs ----
    const int colt = colw_g + tig * 2;
    float hold[4], xpn[4];
    hold[0] = hidden0[(b0 + g) * HID + colt];
    hold[1] = hidden0[(b0 + g) * HID + colt + 1];
    hold[2] = hidden0[(b0 + g + 8) * HID + colt];
    hold[3] = hidden0[(b0 + g + 8) * HID + colt + 1];
    {
        float2 v0 = *(const float2*)(xo + (long)(b0 + g) * HID + colt);
        float2 v1 = *(const float2*)(xo + (long)(b0 + g + 8) * HID + colt);
        xpn[0] = v0.x; xpn[1] = v0.y; xpn[2] = v1.x; xpn[3] = v1.y;
    }

    uint32_t peer_sb[3];
#pragma unroll
    for (int i = 0; i < 3; ++i) {
        uint32_t pr = (rank + 1 + i) & 3;
        asm("mapa.shared::cluster.u32 %0, %1, %2;"
            : "=r"(peer_sb[i]) : "r"(sb), "r"(pr));
    }

    asm volatile("barrier.cluster.arrive.aligned;" ::: "memory");
    asm volatile("barrier.cluster.wait.aligned;" ::: "memory");

    const uint32_t lrow = (lr * ARX2) * 2;
    int p = 0;
    for (int s = 0; s < SEQ; ++s) {
        // acc sets split by kt parity: 8-deep chains
        float aH[2][4], aL1[2][4], aL2[2][4];
#pragma unroll
        for (int i = 0; i < 4; ++i) {
            aH[0][i] = xpn[i]; aH[1][i] = 0.f;
            aL1[0][i] = 0.f; aL1[1][i] = 0.f;
            aL2[0][i] = 0.f; aL2[1][i] = 0.f;
        }

        if (s + 1 < SEQ) {
            float2 v0 = *(const float2*)(xo + ((long)(s + 1) * BATCH + b0 + g) * HID + colt);
            float2 v1 = *(const float2*)(xo + ((long)(s + 1) * BATCH + b0 + g + 8) * HID + colt);
            xpn[0] = v0.x; xpn[1] = v0.y; xpn[2] = v1.x; xpn[3] = v1.y;
        }

        const uint32_t abase = sb + SA_OFF + p * SA_BUF + lrow + ((lane >> 4) * 8) * 2;
#pragma unroll
        for (int kt = 0; kt < 16; ++kt) {
            const int pc = kt & 1;
            uint32_t ah[4], al[4];
            LDSM_X4(ah[0], ah[1], ah[2], ah[3], abase + kt * 32);
            LDSM_X4(al[0], al[1], al[2], al[3], abase + SA_LO + kt * 32);
            MMA16816(aH[pc],  ah, WH[kt]);
            MMA16816(aL1[pc], al, WH[kt]);
            MMA16816(aL2[pc], ah, WL[kt]);
        }

        // ---- epilogue ----
        float pre[4];
#pragma unroll
        for (int i = 0; i < 4; ++i)
            pre[i] = (aH[0][i] + aH[1][i]) + (aL1[0][i] + aL1[1][i])
                   + (aL2[0][i] + aL2[1][i]);

        float v0 = 0.8f * hold[0] + 0.2f * fmaxf(pre[0], 0.f);
        float v1 = 0.8f * hold[1] + 0.2f * fmaxf(pre[1], 0.f);
        float v2 = 0.8f * hold[2] + 0.2f * fmaxf(pre[2], 0.f);
        float v3 = 0.8f * hold[3] + 0.2f * fmaxf(pre[3], 0.f);
        hold[0] = v0; hold[1] = v1; hold[2] = v2; hold[3] = v3;

        const long orow0 = ((long)s * BATCH + b0 + g) * HID + colt;
        const long orow1 = ((long)s * BATCH + b0 + g + 8) * HID + colt;
        *(float2*)(xo + orow0) = make_float2(v0, v1);
        *(float2*)(xo + orow1) = make_float2(v2, v3);

        uint32_t h01; CVTB(h01, v0, v1);
        uint32_t h23; CVTB(h23, v2, v3);
        float f0 = __uint_as_float(h01 << 16);
        float f1 = __uint_as_float(h01 & 0xffff0000u);
        float f2 = __uint_as_float(h23 << 16);
        float f3 = __uint_as_float(h23 & 0xffff0000u);
        uint32_t l01; CVTB(l01, v0 - f0, v1 - f1);
        uint32_t l23; CVTB(l23, v2 - f2, v3 - f3);

        const uint32_t bo = SA_OFF + (p ^ 1) * SA_BUF;
        const uint32_t o0 = bo + (uint32_t)(g * ARX2 + colt) * 2;
        const uint32_t o1 = bo + (uint32_t)((g + 8) * ARX2 + colt) * 2;
        *(uint32_t*)(smem + o0)         = h01;
        *(uint32_t*)(smem + o1)         = h23;
        *(uint32_t*)(smem + SA_LO + o0) = l01;
        *(uint32_t*)(smem + SA_LO + o1) = l23;
#pragma unroll
        for (int i = 0; i < 3; ++i) {
            const uint32_t d = peer_sb[i];
            asm volatile("st.shared::cluster.b32 [%0], %1;"
                         :: "r"(d + o0), "r"(h01) : "memory");
            asm volatile("st.shared::cluster.b32 [%0], %1;"
                         :: "r"(d + o1), "r"(h23) : "memory");
            asm volatile("st.shared::cluster.b32 [%0], %1;"
                         :: "r"(d + SA_LO + o0), "r"(l01) : "memory");
            asm volatile("st.shared::cluster.b32 [%0], %1;"
                         :: "r"(d + SA_LO + o1), "r"(l23) : "memory");
        }

        asm volatile("barrier.cluster.arrive.aligned;" ::: "memory");
        asm volatile("barrier.cluster.wait.aligned;" ::: "memory");
        p ^= 1;
    }

    *(float2*)(hlast + (long)(b0 + g) * HID + colt)     = make_float2(hold[0], hold[1]);
    *(float2*)(hlast + (long)(b0 + g + 8) * HID + colt) = make_float2(hold[2], hold[3]);
}

// ---------------------------------------------------------------------------
extern "C" void kernel_launch(void* const* d_in, const int* in_sizes, int n_in,
                              void* d_out, int out_size) {
    const float* input  = (const float*)d_in[0];
    const float* hidden = (const float*)d_in[1];
    const float* Win    = (const float*)d_in[2];
    const float* b_in   = (const float*)d_in[3];
    const float* Whh    = (const float*)d_in[4];
    const float* b_hh   = (const float*)d_in[5];

    float* out   = (float*)d_out;                          // [SEQ,BATCH,HID]
    float* hlast = out + (long)SEQ * BATCH * HID;          // [BATCH,HID] tail

    cudaFuncSetAttribute(xproj_hmma_kernel,
                         cudaFuncAttributeMaxDynamicSharedMemorySize, XS_TOT);
    xproj_hmma_kernel<<<148, 256, XS_TOT>>>(input, Win, b_in, b_hh, out);

    cudaFuncSetAttribute(rnn_scan_hmma4,
                         cudaFuncAttributeMaxDynamicSharedMemorySize, S_TOTAL);
    rnn_scan_hmma4<<<(BATCH / SCTA) * 4, 256, S_TOTAL>>>(out, hidden, Whh, hlast);
}